// round 8
// baseline (speedup 1.0000x reference)
#include <cuda_runtime.h>
#include <cstdint>

#define NNODES 64
#define NEDGES 128
#define NGRAPH 4

typedef unsigned long long ull;

// layer sizes
#define O1 2000
#define O2 500
#define O3 100
#define K2 2000
#define K3 500
#define NC1 12000
#define NC2 3000
#define NC3 600
#define S2 24
#define S3 32
#define KC2 84
#define KC3 16
#define TILES1 94
#define TILES2 24
#define TILES3 5
#define CB1 63
#define CB2 16
#define CB3 4

// ---------------- scratch ----------------
__device__ float g_Y  [NNODES * NC1];
__device__ float g_Yp [S2 * NNODES * NC2];      // 4.6M floats, reused for L3 partials
__device__ float g_xT [9 * NNODES];
__device__ float g_Pt [384 * NNODES];
__device__ float g_h1T[O1 * NNODES];
__device__ float g_h2T[O2 * NNODES];
__device__ float g_h3 [NNODES * O3];
__device__ int   g_cnt;
__device__ int   g_gen;

// ---------------- helpers ----------------
__device__ __forceinline__ ull dup2(float x) {
    ull r; asm("mov.b64 %0, {%1, %1};" : "=l"(r) : "f"(x)); return r;
}
__device__ __forceinline__ void fma2(ull &d, ull a, ull b) {
    asm("fma.rn.f32x2 %0, %1, %2, %3;" : "=l"(d) : "l"(a), "l"(b), "l"(d));
}
__device__ __forceinline__ float2 unpk(ull v) {
    float2 r; asm("mov.b64 {%0, %1}, %2;" : "=f"(r.x), "=f"(r.y) : "l"(v)); return r;
}
__device__ __forceinline__ void cpa16(void* dst, const void* src) {
    uint32_t d = (uint32_t)__cvta_generic_to_shared(dst);
    asm volatile("cp.async.cg.shared.global [%0], [%1], 16;\n" :: "r"(d), "l"(src));
}
__device__ __forceinline__ void cpa_commit() {
    asm volatile("cp.async.commit_group;\n" ::: "memory");
}
template<int N> __device__ __forceinline__ void cpa_wait() {
    asm volatile("cp.async.wait_group %0;\n" :: "n"(N) : "memory");
}

// device-wide barrier (all blocks resident by construction)
__device__ __forceinline__ void gbar() {
    __syncthreads();
    if (threadIdx.x == 0) {
        __threadfence();
        volatile int* vg = &g_gen;
        int gen = *vg;
        int tk = atomicAdd(&g_cnt, 1);
        if (tk == (int)gridDim.x - 1) {
            g_cnt = 0;
            __threadfence();
            *vg = gen + 1;
        } else {
            while (*vg == gen) { __nanosleep(200); }
            __threadfence();
        }
    }
    __syncthreads();
}

// ---------------- GEMM virtual block: BM=64, BN=128, BK=16, 8x8 f32x2 ----------------
__device__ void gemm_vb(int c0, int k0, int kend, int K, int O, int NC,
                        const float* __restrict__ AT, const float* __restrict__ We,
                        const float* __restrict__ be, const float* __restrict__ root,
                        float* __restrict__ Yo, char* smraw)
{
    float (*As)[16][68]  = (float (*)[16][68])smraw;
    float (*Bs)[16][128] = (float (*)[16][128])(smraw + 13056);

    const int t = threadIdx.x;
    const int nsteps = (kend - k0 + 15) >> 4;
    const int kkB = t >> 3;
    const int cbase = (t & 7) * 16;
    const float4 z4 = make_float4(0.f, 0.f, 0.f, 0.f);

    auto stage = [&](int s, int buf) {
        const int kt = k0 + s * 16;
        const int kb = kend - kt;
        #pragma unroll
        for (int i = 0; i < 4; i++) {
            int cl = cbase + 4 * i;
            int c  = c0 + cl;
            float4* bd = (float4*)&Bs[buf][kkB][cl];
            if (kkB < kb && c < NC) {
                int blk = c / O;
                int o   = c - blk * O;
                const float* P = (blk < 4) ? (We + (size_t)blk * K * O)
                                           : ((blk == 4) ? be : root);
                cpa16(bd, P + (size_t)(kt + kkB) * O + o);
            } else *bd = z4;
        }
        #pragma unroll
        for (int i = 0; i < 2; i++) {
            int q  = t + 128 * i;
            int kk = q >> 4, m4 = (q & 15) * 4;
            float4* ad = (float4*)&As[buf][kk][m4];
            if (kk < kb) cpa16(ad, AT + (size_t)(kt + kk) * NNODES + m4);
            else         *ad = z4;
        }
        cpa_commit();
    };

    stage(0, 0);
    if (nsteps > 1) stage(1, 1);

    const int tx = t & 15;
    const int ty = t >> 4;
    ull acc[4][8];
    #pragma unroll
    for (int r = 0; r < 4; r++)
        #pragma unroll
        for (int j = 0; j < 8; j++) acc[r][j] = 0ull;

    for (int s = 0; s < nsteps; s++) {
        const int buf = s % 3;
        if (s + 2 < nsteps)      { stage(s + 2, (s + 2) % 3); cpa_wait<2>(); }
        else if (s + 1 < nsteps) { cpa_wait<1>(); }
        else                     { cpa_wait<0>(); }
        __syncthreads();

        #pragma unroll
        for (int kk = 0; kk < 16; kk++) {
            const float* as = &As[buf][kk][8 * ty];
            ull a0 = *(const ull*)(as);
            ull a1 = *(const ull*)(as + 2);
            ull a2 = *(const ull*)(as + 4);
            ull a3 = *(const ull*)(as + 6);
            float4 bL = *(const float4*)&Bs[buf][kk][4 * tx];
            float4 bH = *(const float4*)&Bs[buf][kk][64 + 4 * tx];
            ull b0 = dup2(bL.x), b1 = dup2(bL.y), b2 = dup2(bL.z), b3 = dup2(bL.w);
            ull b4 = dup2(bH.x), b5 = dup2(bH.y), b6 = dup2(bH.z), b7 = dup2(bH.w);
            fma2(acc[0][0], a0, b0); fma2(acc[0][1], a0, b1); fma2(acc[0][2], a0, b2); fma2(acc[0][3], a0, b3);
            fma2(acc[0][4], a0, b4); fma2(acc[0][5], a0, b5); fma2(acc[0][6], a0, b6); fma2(acc[0][7], a0, b7);
            fma2(acc[1][0], a1, b0); fma2(acc[1][1], a1, b1); fma2(acc[1][2], a1, b2); fma2(acc[1][3], a1, b3);
            fma2(acc[1][4], a1, b4); fma2(acc[1][5], a1, b5); fma2(acc[1][6], a1, b6); fma2(acc[1][7], a1, b7);
            fma2(acc[2][0], a2, b0); fma2(acc[2][1], a2, b1); fma2(acc[2][2], a2, b2); fma2(acc[2][3], a2, b3);
            fma2(acc[2][4], a2, b4); fma2(acc[2][5], a2, b5); fma2(acc[2][6], a2, b6); fma2(acc[2][7], a2, b7);
            fma2(acc[3][0], a3, b0); fma2(acc[3][1], a3, b1); fma2(acc[3][2], a3, b2); fma2(acc[3][3], a3, b3);
            fma2(acc[3][4], a3, b4); fma2(acc[3][5], a3, b5); fma2(acc[3][6], a3, b6); fma2(acc[3][7], a3, b7);
        }
        __syncthreads();
    }

    const int cL = c0 + 4 * tx;
    const int cH = c0 + 64 + 4 * tx;
    #pragma unroll
    for (int rp = 0; rp < 4; rp++) {
        int m = 8 * ty + 2 * rp;
        float2 vL0 = unpk(acc[rp][0]), vL1 = unpk(acc[rp][1]);
        float2 vL2 = unpk(acc[rp][2]), vL3 = unpk(acc[rp][3]);
        float2 vH0 = unpk(acc[rp][4]), vH1 = unpk(acc[rp][5]);
        float2 vH2 = unpk(acc[rp][6]), vH3 = unpk(acc[rp][7]);
        if (cL < NC) {
            *(float4*)&Yo[(size_t)m       * NC + cL] = make_float4(vL0.x, vL1.x, vL2.x, vL3.x);
            *(float4*)&Yo[(size_t)(m + 1) * NC + cL] = make_float4(vL0.y, vL1.y, vL2.y, vL3.y);
        }
        if (cH < NC) {
            *(float4*)&Yo[(size_t)m       * NC + cH] = make_float4(vH0.x, vH1.x, vH2.x, vH3.x);
            *(float4*)&Yo[(size_t)(m + 1) * NC + cH] = make_float4(vH0.y, vH1.y, vH2.y, vH3.y);
        }
    }
}

// ---------------- combine virtual block: h = relu(P^T @ Yg + b), BN=32, K=384 ----------------
__device__ void combine_vb(int c0, int O, int NC,
                           const float* __restrict__ Y, const float* __restrict__ Pt,
                           const float* __restrict__ bias, float* __restrict__ h,
                           float* __restrict__ hT, bool want_h, bool want_hT,
                           char* smraw)
{
    float (*As)[16][68] = (float (*)[16][68])smraw;
    float (*Bs)[16][32] = (float (*)[16][32])(smraw + 13056);

    const int t = threadIdx.x;
    const int kkB = t >> 3;
    const int clB = (t & 7) * 4;
    const bool bvalid = (c0 + clB < O);
    const float4 z4 = make_float4(0.f, 0.f, 0.f, 0.f);

    auto stage = [&](int s, int buf) {
        int r = s * 16 + kkB;
        int sN, jb;
        if (r < 320) { sN = r / 5; jb = r - 5 * sN; }
        else         { sN = r - 320; jb = 5; }
        float4* bd = (float4*)&Bs[buf][kkB][clB];
        if (bvalid) cpa16(bd, Y + (size_t)sN * NC + (size_t)jb * O + c0 + clB);
        else        *bd = z4;
        #pragma unroll
        for (int i = 0; i < 2; i++) {
            int q  = t + 128 * i;
            int kk = q >> 4, m4 = (q & 15) * 4;
            cpa16(&As[buf][kk][m4], Pt + (size_t)(s * 16 + kk) * NNODES + m4);
        }
        cpa_commit();
    };

    stage(0, 0);
    stage(1, 1);

    const int tx = t & 7;
    const int ty = t >> 3;
    ull acc[2][4];
    #pragma unroll
    for (int r = 0; r < 2; r++)
        #pragma unroll
        for (int j = 0; j < 4; j++) acc[r][j] = 0ull;

    for (int s = 0; s < 24; s++) {
        const int buf = s % 3;
        if (s + 2 < 24)      { stage(s + 2, (s + 2) % 3); cpa_wait<2>(); }
        else if (s + 1 < 24) { cpa_wait<1>(); }
        else                 { cpa_wait<0>(); }
        __syncthreads();

        #pragma unroll
        for (int kk = 0; kk < 16; kk++) {
            const float* as = &As[buf][kk][0];
            ull a0 = *(const ull*)(as + 4 * ty);
            ull a1 = *(const ull*)(as + 4 * ty + 2);
            float4 b = *(const float4*)&Bs[buf][kk][4 * tx];
            ull b0 = dup2(b.x), b1 = dup2(b.y), b2 = dup2(b.z), b3 = dup2(b.w);
            fma2(acc[0][0], a0, b0); fma2(acc[0][1], a0, b1);
            fma2(acc[0][2], a0, b2); fma2(acc[0][3], a0, b3);
            fma2(acc[1][0], a1, b0); fma2(acc[1][1], a1, b1);
            fma2(acc[1][2], a1, b2); fma2(acc[1][3], a1, b3);
        }
        __syncthreads();
    }

    const int c = c0 + 4 * tx;
    if (c < O) {
        float4 bb = *(const float4*)&bias[c];
        float2 v[2][4];
        #pragma unroll
        for (int r = 0; r < 2; r++)
            #pragma unroll
            for (int j = 0; j < 4; j++) v[r][j] = unpk(acc[r][j]);
        float row[4][4];
        #pragma unroll
        for (int j = 0; j < 4; j++) {
            float bj = (&bb.x)[j];
            row[0][j] = fmaxf(v[0][j].x + bj, 0.f);
            row[1][j] = fmaxf(v[0][j].y + bj, 0.f);
            row[2][j] = fmaxf(v[1][j].x + bj, 0.f);
            row[3][j] = fmaxf(v[1][j].y + bj, 0.f);
        }
        const int m0 = 4 * ty;
        if (want_h) {
            #pragma unroll
            for (int r = 0; r < 4; r++)
                *(float4*)&h[(size_t)(m0 + r) * O + c] =
                    make_float4(row[r][0], row[r][1], row[r][2], row[r][3]);
        }
        if (want_hT) {
            #pragma unroll
            for (int j = 0; j < 4; j++)
                *(float4*)&hT[(size_t)(c + j) * NNODES + m0] =
                    make_float4(row[0][j], row[1][j], row[2][j], row[3][j]);
        }
    }
}

// ---------------- head virtual block (one graph), 128 threads ----------------
__device__ void head_vb(int g, const int* __restrict__ batch,
                        const float* __restrict__ W1, const float* __restrict__ c1,
                        const float* __restrict__ W2, const float* __restrict__ c2,
                        const float* __restrict__ W3, const float* __restrict__ c3,
                        const float* __restrict__ W4, const float* __restrict__ c4,
                        float* __restrict__ out, char* smraw)
{
    float* gS   = (float*)smraw;        // 100 (pad to 128)
    float* s1   = gS + 128;             // 1000
    float* part = s1 + 1000;            // 200
    float* s2   = part + 200;           // 100 (pad to 128)
    float* s3   = s2 + 128;             // 50 (pad to 64)
    int*   sb   = (int*)(s3 + 64);      // 64

    const int t = threadIdx.x;
    if (t < NNODES) sb[t] = batch[t];
    __syncthreads();

    if (t < 100) {
        float a = 0.f;
        for (int n = 0; n < NNODES; n++)
            if (sb[n] == g) a += __ldcg(&g_h3[n * 100 + t]);
        gS[t] = a;
    }
    __syncthreads();

    for (int f = t; f < 1000; f += 128) {
        float a = c1[f];
        for (int k = 0; k < 100; k++) a += gS[k] * W1[k * 1000 + f];
        s1[f] = fmaxf(a, 0.f);
    }
    __syncthreads();

    for (int idx = t; idx < 200; idx += 128) {
        int f = idx % 100, hh = idx / 100;
        float a = 0.f;
        int k0 = hh * 500;
        for (int k = k0; k < k0 + 500; k++) a += s1[k] * W2[k * 100 + f];
        part[idx] = a;
    }
    __syncthreads();
    if (t < 100) s2[t] = fmaxf(part[t] + part[100 + t] + c2[t], 0.f);
    __syncthreads();

    if (t < 50) {
        float a = c3[t];
        for (int k = 0; k < 100; k++) a += s2[k] * W3[k * 50 + t];
        s3[t] = fmaxf(a, 0.f);
    }
    __syncthreads();

    if (t < 32) {
        float a = (t < 50) ? s3[t] * W4[t] : 0.f;
        if (t + 32 < 50) a += s3[t + 32] * W4[t + 32];
        #pragma unroll
        for (int o = 16; o > 0; o >>= 1)
            a += __shfl_xor_sync(0xffffffffu, a, o);
        if (t == 0) out[g] = a + c4[0];
    }
}

// ---------------- the persistent mega-kernel ----------------
__global__ __launch_bounds__(128, 4) void mega(
    const float* __restrict__ x, const int* __restrict__ eidx,
    const float* __restrict__ eattr, const int* __restrict__ batch,
    const float* We1, const float* be1, const float* ro1, const float* b1,
    const float* We2, const float* be2, const float* ro2, const float* b2,
    const float* We3, const float* be3, const float* ro3, const float* b3,
    const float* W1, const float* c1, const float* W2, const float* c2,
    const float* W3, const float* c3, const float* W4, const float* c4,
    float* out)
{
    __shared__ __align__(16) char sm[37632];
    const int t    = threadIdx.x;
    const int gid  = blockIdx.x * 128 + t;
    const int gstr = gridDim.x * 128;

    // ---- A0: init Pt (zeros + root-identity) and xT ----
    for (int i = gid; i < 384 * NNODES; i += gstr) {
        int r = i >> 6, n = i & 63;
        g_Pt[i] = (r >= 320 && (r - 320) == n) ? 1.f : 0.f;
    }
    for (int i = gid; i < NNODES * 9; i += gstr) {
        int m = i / 9, a = i - 9 * m;
        g_xT[a * NNODES + m] = x[i];
    }
    gbar();

    // ---- A1: edge atomics into Pt (block 0) + layer-1 GEMM ----
    if (blockIdx.x == 0 && t < NEDGES) {
        int s = eidx[t], d = eidx[NEDGES + t];
        #pragma unroll
        for (int j = 0; j < 4; j++)
            atomicAdd(&g_Pt[(s * 5 + j) * NNODES + d], eattr[t * 4 + j]);
        atomicAdd(&g_Pt[(s * 5 + 4) * NNODES + d], 1.f);
    }
    for (int vb = blockIdx.x; vb < TILES1; vb += gridDim.x)
        gemm_vb(vb * 128, 0, 9, 9, O1, NC1, g_xT, We1, be1, ro1, g_Y, sm);
    gbar();

    // ---- B: combine layer 1 -> h1T ----
    for (int vb = blockIdx.x; vb < CB1; vb += gridDim.x)
        combine_vb(vb * 32, O1, NC1, g_Y, g_Pt, b1, nullptr, g_h1T, false, true, sm);
    gbar();

    // ---- C: layer-2 GEMM (24 tiles x 24 K-slices) -> Yp ----
    for (int vb = blockIdx.x; vb < TILES2 * S2; vb += gridDim.x) {
        int bx = vb % TILES2, by = vb / TILES2;
        int k0 = by * KC2;
        int kend = min(k0 + KC2, K2);
        gemm_vb(bx * 128, k0, kend, K2, O2, NC2, g_h1T, We2, be2, ro2,
                g_Yp + (size_t)by * NNODES * NC2, sm);
    }
    gbar();

    // ---- D1: reduce layer-2 split-K -> Y ----
    for (int i = gid; i < NNODES * NC2; i += gstr) {
        float a = 0.f;
        #pragma unroll 4
        for (int j = 0; j < S2; j++) a += __ldcg(&g_Yp[(size_t)j * NNODES * NC2 + i]);
        g_Y[i] = a;
    }
    gbar();

    // ---- D2: combine layer 2 -> h2T ----
    for (int vb = blockIdx.x; vb < CB2; vb += gridDim.x)
        combine_vb(vb * 32, O2, NC2, g_Y, g_Pt, b2, nullptr, g_h2T, false, true, sm);
    gbar();

    // ---- E: layer-3 GEMM (5 tiles x 32 K-slices) -> Yp ----
    for (int vb = blockIdx.x; vb < TILES3 * S3; vb += gridDim.x) {
        int bx = vb % TILES3, by = vb / TILES3;
        int k0 = by * KC3;
        int kend = min(k0 + KC3, K3);
        gemm_vb(bx * 128, k0, kend, K3, O3, NC3, g_h2T, We3, be3, ro3,
                g_Yp + (size_t)by * NNODES * NC3, sm);
    }
    gbar();

    // ---- F1: reduce layer-3 split-K -> Y ----
    for (int i = gid; i < NNODES * NC3; i += gstr) {
        float a = 0.f;
        #pragma unroll 4
        for (int j = 0; j < S3; j++) a += __ldcg(&g_Yp[(size_t)j * NNODES * NC3 + i]);
        g_Y[i] = a;
    }
    gbar();

    // ---- F2: combine layer 3 -> h3 (row-major) ----
    for (int vb = blockIdx.x; vb < CB3; vb += gridDim.x)
        combine_vb(vb * 32, O3, NC3, g_Y, g_Pt, b3, g_h3, nullptr, true, false, sm);
    gbar();

    // ---- G: fused FCN head ----
    for (int vb = blockIdx.x; vb < NGRAPH; vb += gridDim.x)
        head_vb(vb, batch, W1, c1, W2, c2, W3, c3, W4, c4, out, sm);
}

// ---------------- launch ----------------
extern "C" void kernel_launch(void* const* d_in, const int* in_sizes, int n_in,
                              void* d_out, int out_size)
{
    const float* x     = (const float*)d_in[0];
    const int*   eidx  = (const int*)  d_in[1];
    const float* eattr = (const float*)d_in[2];
    const int*   batch = (const int*)  d_in[3];
    const float *We1 = (const float*)d_in[4],  *be1 = (const float*)d_in[5];
    const float *ro1 = (const float*)d_in[6],  *b1  = (const float*)d_in[7];
    const float *We2 = (const float*)d_in[8],  *be2 = (const float*)d_in[9];
    const float *ro2 = (const float*)d_in[10], *b2  = (const float*)d_in[11];
    const float *We3 = (const float*)d_in[12], *be3 = (const float*)d_in[13];
    const float *ro3 = (const float*)d_in[14], *b3  = (const float*)d_in[15];
    const float *W1  = (const float*)d_in[16], *c1  = (const float*)d_in[17];
    const float *W2  = (const float*)d_in[18], *c2  = (const float*)d_in[19];
    const float *W3  = (const float*)d_in[20], *c3  = (const float*)d_in[21];
    const float *W4  = (const float*)d_in[22], *c4  = (const float*)d_in[23];

    int nsm = 148;
    cudaDeviceGetAttribute(&nsm, cudaDevAttrMultiProcessorCount, 0);
    int occ = 1;
    cudaOccupancyMaxActiveBlocksPerMultiprocessor(&occ, mega, 128, 0);
    if (occ < 1) occ = 1;
    if (occ > 4) occ = 4;
    int grid = occ * nsm;

    mega<<<grid, 128>>>(x, eidx, eattr, batch,
                        We1, be1, ro1, b1,
                        We2, be2, ro2, b2,
                        We3, be3, ro3, b3,
                        W1, c1, W2, c2, W3, c3, W4, c4,
                        (float*)d_out);
}

// round 9
// speedup vs baseline: 1.3423x; 1.3423x over previous
#include <cuda_runtime.h>
#include <cstdint>

#define NNODES 64
#define NEDGES 128
#define NGRAPH 4

typedef unsigned long long ull;

#define O1 2000
#define O2 500
#define O3 100
#define NC1 12000
#define NC2 3000
#define NC3 600
#define S2 24
#define KC2 84
#define S3 32
#define KC3 16
#define TILES1 94
#define TILES2 24
#define TILES3 5
#define CB1 63
#define CB2 16
#define CB3 4

// ---------------- scratch ----------------
__device__ float g_Y   [NNODES * NC1];                    // layer-1 GEMM out
__device__ float g_Yacc[NNODES * NC2 + NNODES * NC3];     // atomic accumulators L2|L3
__device__ float g_Pt  [384 * NNODES];
__device__ float g_h1T [O1 * NNODES];
__device__ float g_h2T [O2 * NNODES];
__device__ float g_h3  [NNODES * O3];

// ---------------- helpers ----------------
__device__ __forceinline__ void gdc_wait() {
    asm volatile("griddepcontrol.wait;" ::: "memory");
}
__device__ __forceinline__ void gdc_launch() {
    asm volatile("griddepcontrol.launch_dependents;" ::: "memory");
}
__device__ __forceinline__ ull dup2(float x) {
    ull r; asm("mov.b64 %0, {%1, %1};" : "=l"(r) : "f"(x)); return r;
}
__device__ __forceinline__ void fma2(ull &d, ull a, ull b) {
    asm("fma.rn.f32x2 %0, %1, %2, %3;" : "=l"(d) : "l"(a), "l"(b), "l"(d));
}
__device__ __forceinline__ float2 unpk(ull v) {
    float2 r; asm("mov.b64 {%0, %1}, %2;" : "=f"(r.x), "=f"(r.y) : "l"(v)); return r;
}
__device__ __forceinline__ void cpa16(void* dst, const void* src) {
    uint32_t d = (uint32_t)__cvta_generic_to_shared(dst);
    asm volatile("cp.async.cg.shared.global [%0], [%1], 16;\n" :: "r"(d), "l"(src));
}
__device__ __forceinline__ void cpa_commit() {
    asm volatile("cp.async.commit_group;\n" ::: "memory");
}
template<int N> __device__ __forceinline__ void cpa_wait() {
    asm volatile("cp.async.wait_group %0;\n" :: "n"(N) : "memory");
}

// ================= gemm1: K=9 special; fuses prep (Pt build, Yacc zero) =================
// grid = 96: blocks 0..93 tiles (BN=128), block 94 builds Pt, block 95 just zeroes.
__global__ __launch_bounds__(128) void gemm1(
    const float* __restrict__ x, const int* __restrict__ eidx,
    const float* __restrict__ eattr,
    const float* __restrict__ We, const float* __restrict__ be,
    const float* __restrict__ root, float* __restrict__ Y)
{
    __shared__ float As[16][68];
    __shared__ float Bs[16][128];

    gdc_wait();
    gdc_launch();

    const int t = threadIdx.x;

    // zero the atomic accumulators (spread over all blocks)
    {
        float4* Z4 = (float4*)g_Yacc;
        const int tot4 = (NNODES * NC2 + NNODES * NC3) / 4;
        for (int i = blockIdx.x * 128 + t; i < tot4; i += 96 * 128)
            Z4[i] = make_float4(0.f, 0.f, 0.f, 0.f);
    }

    if (blockIdx.x == 94) {
        // build Pt
        for (int i = t; i < 384 * NNODES; i += 128) {
            int r = i >> 6, n = i & 63;
            g_Pt[i] = (r >= 320 && (r - 320) == n) ? 1.f : 0.f;
        }
        __syncthreads();
        if (t < NEDGES) {
            int s = eidx[t], d = eidx[NEDGES + t];
            #pragma unroll
            for (int j = 0; j < 4; j++)
                atomicAdd(&g_Pt[(s * 5 + j) * NNODES + d], eattr[t * 4 + j]);
            atomicAdd(&g_Pt[(s * 5 + 4) * NNODES + d], 1.f);
        }
        return;
    }
    if (blockIdx.x >= 94) return;

    const int c0 = blockIdx.x * 128;

    // stage B (9 rows, zero-pad to 16)
    {
        const int kkB   = t >> 3;
        const int cbase = (t & 7) * 16;
        const float4 z4 = make_float4(0.f, 0.f, 0.f, 0.f);
        #pragma unroll
        for (int i = 0; i < 4; i++) {
            int cl = cbase + 4 * i;
            int c  = c0 + cl;
            float4* bd = (float4*)&Bs[kkB][cl];
            if (kkB < 9 && c < NC1) {
                int blk = c / O1;
                int o   = c - blk * O1;
                const float* P = (blk < 4) ? (We + (size_t)blk * 9 * O1)
                                           : ((blk == 4) ? be : root);
                cpa16(bd, P + (size_t)kkB * O1 + o);
            } else *bd = z4;
        }
        cpa_commit();
    }
    // stage A: transpose x in-block
    if (t < NNODES) {
        #pragma unroll
        for (int a = 0; a < 9; a++) As[a][t] = x[t * 9 + a];
    }
    cpa_wait<0>();
    __syncthreads();

    const int tx = t & 15;
    const int ty = t >> 4;
    ull acc[4][8];
    #pragma unroll
    for (int r = 0; r < 4; r++)
        #pragma unroll
        for (int j = 0; j < 8; j++) acc[r][j] = 0ull;

    #pragma unroll
    for (int kk = 0; kk < 9; kk++) {
        const float* as = &As[kk][8 * ty];
        ull a0 = *(const ull*)(as);
        ull a1 = *(const ull*)(as + 2);
        ull a2 = *(const ull*)(as + 4);
        ull a3 = *(const ull*)(as + 6);
        float4 bL = *(const float4*)&Bs[kk][4 * tx];
        float4 bH = *(const float4*)&Bs[kk][64 + 4 * tx];
        ull b0 = dup2(bL.x), b1 = dup2(bL.y), b2 = dup2(bL.z), b3 = dup2(bL.w);
        ull b4 = dup2(bH.x), b5 = dup2(bH.y), b6 = dup2(bH.z), b7 = dup2(bH.w);
        fma2(acc[0][0], a0, b0); fma2(acc[0][1], a0, b1); fma2(acc[0][2], a0, b2); fma2(acc[0][3], a0, b3);
        fma2(acc[0][4], a0, b4); fma2(acc[0][5], a0, b5); fma2(acc[0][6], a0, b6); fma2(acc[0][7], a0, b7);
        fma2(acc[1][0], a1, b0); fma2(acc[1][1], a1, b1); fma2(acc[1][2], a1, b2); fma2(acc[1][3], a1, b3);
        fma2(acc[1][4], a1, b4); fma2(acc[1][5], a1, b5); fma2(acc[1][6], a1, b6); fma2(acc[1][7], a1, b7);
        fma2(acc[2][0], a2, b0); fma2(acc[2][1], a2, b1); fma2(acc[2][2], a2, b2); fma2(acc[2][3], a2, b3);
        fma2(acc[2][4], a2, b4); fma2(acc[2][5], a2, b5); fma2(acc[2][6], a2, b6); fma2(acc[2][7], a2, b7);
        fma2(acc[3][0], a3, b0); fma2(acc[3][1], a3, b1); fma2(acc[3][2], a3, b2); fma2(acc[3][3], a3, b3);
        fma2(acc[3][4], a3, b4); fma2(acc[3][5], a3, b5); fma2(acc[3][6], a3, b6); fma2(acc[3][7], a3, b7);
    }

    const int cL = c0 + 4 * tx;
    const int cH = c0 + 64 + 4 * tx;
    #pragma unroll
    for (int rp = 0; rp < 4; rp++) {
        int m = 8 * ty + 2 * rp;
        float2 vL0 = unpk(acc[rp][0]), vL1 = unpk(acc[rp][1]);
        float2 vL2 = unpk(acc[rp][2]), vL3 = unpk(acc[rp][3]);
        float2 vH0 = unpk(acc[rp][4]), vH1 = unpk(acc[rp][5]);
        float2 vH2 = unpk(acc[rp][6]), vH3 = unpk(acc[rp][7]);
        if (cL < NC1) {
            *(float4*)&Y[(size_t)m       * NC1 + cL] = make_float4(vL0.x, vL1.x, vL2.x, vL3.x);
            *(float4*)&Y[(size_t)(m + 1) * NC1 + cL] = make_float4(vL0.y, vL1.y, vL2.y, vL3.y);
        }
        if (cH < NC1) {
            *(float4*)&Y[(size_t)m       * NC1 + cH] = make_float4(vH0.x, vH1.x, vH2.x, vH3.x);
            *(float4*)&Y[(size_t)(m + 1) * NC1 + cH] = make_float4(vH0.y, vH1.y, vH2.y, vH3.y);
        }
    }
}

// ================= gemm_atomic: split-K GEMM, atomicAdd epilogue =================
// BM=64, BN=128, BK=16, 8x8 f32x2, 3-stage cp.async. grid (tiles, slices).
__global__ __launch_bounds__(128) void gemm_atomic(
    const float* __restrict__ AT, int K, int O,
    const float* __restrict__ We, const float* __restrict__ be,
    const float* __restrict__ root, float* __restrict__ Yacc, int kChunk)
{
    __shared__ float As[3][16][68];
    __shared__ float Bs[3][16][128];

    gdc_wait();
    gdc_launch();

    const int t    = threadIdx.x;
    const int NC   = 6 * O;
    const int c0   = blockIdx.x * 128;
    const int k0   = blockIdx.y * kChunk;
    const int kend = min(k0 + kChunk, K);
    const int nsteps = (kend - k0 + 15) >> 4;

    const int kkB   = t >> 3;
    const int cbase = (t & 7) * 16;
    const float4 z4 = make_float4(0.f, 0.f, 0.f, 0.f);

    auto stage = [&](int s, int buf) {
        const int kt = k0 + s * 16;
        const int kb = kend - kt;
        #pragma unroll
        for (int i = 0; i < 4; i++) {
            int cl = cbase + 4 * i;
            int c  = c0 + cl;
            float4* bd = (float4*)&Bs[buf][kkB][cl];
            if (kkB < kb && c < NC) {
                int blk = c / O;
                int o   = c - blk * O;
                const float* P = (blk < 4) ? (We + (size_t)blk * K * O)
                                           : ((blk == 4) ? be : root);
                cpa16(bd, P + (size_t)(kt + kkB) * O + o);
            } else *bd = z4;
        }
        #pragma unroll
        for (int i = 0; i < 2; i++) {
            int q  = t + 128 * i;
            int kk = q >> 4, m4 = (q & 15) * 4;
            float4* ad = (float4*)&As[buf][kk][m4];
            if (kk < kb) cpa16(ad, AT + (size_t)(kt + kk) * NNODES + m4);
            else         *ad = z4;
        }
        cpa_commit();
    };

    stage(0, 0);
    if (nsteps > 1) stage(1, 1);

    const int tx = t & 15;
    const int ty = t >> 4;
    ull acc[4][8];
    #pragma unroll
    for (int r = 0; r < 4; r++)
        #pragma unroll
        for (int j = 0; j < 8; j++) acc[r][j] = 0ull;

    for (int s = 0; s < nsteps; s++) {
        const int buf = s % 3;
        if (s + 2 < nsteps)      { stage(s + 2, (s + 2) % 3); cpa_wait<2>(); }
        else if (s + 1 < nsteps) { cpa_wait<1>(); }
        else                     { cpa_wait<0>(); }
        __syncthreads();

        #pragma unroll
        for (int kk = 0; kk < 16; kk++) {
            const float* as = &As[buf][kk][8 * ty];
            ull a0 = *(const ull*)(as);
            ull a1 = *(const ull*)(as + 2);
            ull a2 = *(const ull*)(as + 4);
            ull a3 = *(const ull*)(as + 6);
            float4 bL = *(const float4*)&Bs[buf][kk][4 * tx];
            float4 bH = *(const float4*)&Bs[buf][kk][64 + 4 * tx];
            ull b0 = dup2(bL.x), b1 = dup2(bL.y), b2 = dup2(bL.z), b3 = dup2(bL.w);
            ull b4 = dup2(bH.x), b5 = dup2(bH.y), b6 = dup2(bH.z), b7 = dup2(bH.w);
            fma2(acc[0][0], a0, b0); fma2(acc[0][1], a0, b1); fma2(acc[0][2], a0, b2); fma2(acc[0][3], a0, b3);
            fma2(acc[0][4], a0, b4); fma2(acc[0][5], a0, b5); fma2(acc[0][6], a0, b6); fma2(acc[0][7], a0, b7);
            fma2(acc[1][0], a1, b0); fma2(acc[1][1], a1, b1); fma2(acc[1][2], a1, b2); fma2(acc[1][3], a1, b3);
            fma2(acc[1][4], a1, b4); fma2(acc[1][5], a1, b5); fma2(acc[1][6], a1, b6); fma2(acc[1][7], a1, b7);
            fma2(acc[2][0], a2, b0); fma2(acc[2][1], a2, b1); fma2(acc[2][2], a2, b2); fma2(acc[2][3], a2, b3);
            fma2(acc[2][4], a2, b4); fma2(acc[2][5], a2, b5); fma2(acc[2][6], a2, b6); fma2(acc[2][7], a2, b7);
            fma2(acc[3][0], a3, b0); fma2(acc[3][1], a3, b1); fma2(acc[3][2], a3, b2); fma2(acc[3][3], a3, b3);
            fma2(acc[3][4], a3, b4); fma2(acc[3][5], a3, b5); fma2(acc[3][6], a3, b6); fma2(acc[3][7], a3, b7);
        }
        __syncthreads();
    }

    const int cL = c0 + 4 * tx;
    const int cH = c0 + 64 + 4 * tx;
    #pragma unroll
    for (int rp = 0; rp < 4; rp++) {
        int m = 8 * ty + 2 * rp;
        float2 v[8];
        #pragma unroll
        for (int j = 0; j < 8; j++) v[j] = unpk(acc[rp][j]);
        if (cL < NC) {
            #pragma unroll
            for (int j = 0; j < 4; j++) {
                atomicAdd(&Yacc[(size_t)m       * NC + cL + j], v[j].x);
                atomicAdd(&Yacc[(size_t)(m + 1) * NC + cL + j], v[j].y);
            }
        }
        if (cH < NC) {
            #pragma unroll
            for (int j = 0; j < 4; j++) {
                atomicAdd(&Yacc[(size_t)m       * NC + cH + j], v[4 + j].x);
                atomicAdd(&Yacc[(size_t)(m + 1) * NC + cH + j], v[4 + j].y);
            }
        }
    }
}

// ================= combine: h = relu(P^T @ Yg + b), BN=32, K=384, 3-stage =================
__global__ __launch_bounds__(128) void combine_gemm(
    const float* __restrict__ Y, int O, const float* __restrict__ bias,
    float* __restrict__ h, float* __restrict__ hT, int want_h, int want_hT)
{
    __shared__ float As[3][16][68];
    __shared__ float Bs[3][16][32];

    gdc_wait();
    gdc_launch();

    const int t  = threadIdx.x;
    const int NC = 6 * O;
    const int c0 = blockIdx.x * 32;

    const int kkB = t >> 3;
    const int clB = (t & 7) * 4;
    const bool bvalid = (c0 + clB < O);
    const float4 z4 = make_float4(0.f, 0.f, 0.f, 0.f);

    auto stage = [&](int s, int buf) {
        int r = s * 16 + kkB;
        int sN, jb;
        if (r < 320) { sN = r / 5; jb = r - 5 * sN; }
        else         { sN = r - 320; jb = 5; }
        float4* bd = (float4*)&Bs[buf][kkB][clB];
        if (bvalid) cpa16(bd, Y + (size_t)sN * NC + (size_t)jb * O + c0 + clB);
        else        *bd = z4;
        #pragma unroll
        for (int i = 0; i < 2; i++) {
            int q  = t + 128 * i;
            int kk = q >> 4, m4 = (q & 15) * 4;
            cpa16(&As[buf][kk][m4], g_Pt + (size_t)(s * 16 + kk) * NNODES + m4);
        }
        cpa_commit();
    };

    stage(0, 0);
    stage(1, 1);

    const int tx = t & 7;
    const int ty = t >> 3;
    ull acc[2][4];
    #pragma unroll
    for (int r = 0; r < 2; r++)
        #pragma unroll
        for (int j = 0; j < 4; j++) acc[r][j] = 0ull;

    for (int s = 0; s < 24; s++) {
        const int buf = s % 3;
        if (s + 2 < 24)      { stage(s + 2, (s + 2) % 3); cpa_wait<2>(); }
        else if (s + 1 < 24) { cpa_wait<1>(); }
        else                 { cpa_wait<0>(); }
        __syncthreads();

        #pragma unroll
        for (int kk = 0; kk < 16; kk++) {
            const float* as = &As[buf][kk][0];
            ull a0 = *(const ull*)(as + 4 * ty);
            ull a1 = *(const ull*)(as + 4 * ty + 2);
            float4 b = *(const float4*)&Bs[buf][kk][4 * tx];
            ull b0 = dup2(b.x), b1 = dup2(b.y), b2 = dup2(b.z), b3 = dup2(b.w);
            fma2(acc[0][0], a0, b0); fma2(acc[0][1], a0, b1);
            fma2(acc[0][2], a0, b2); fma2(acc[0][3], a0, b3);
            fma2(acc[1][0], a1, b0); fma2(acc[1][1], a1, b1);
            fma2(acc[1][2], a1, b2); fma2(acc[1][3], a1, b3);
        }
        __syncthreads();
    }

    const int c = c0 + 4 * tx;
    if (c < O) {
        float4 bb = *(const float4*)&bias[c];
        float2 v[2][4];
        #pragma unroll
        for (int r = 0; r < 2; r++)
            #pragma unroll
            for (int j = 0; j < 4; j++) v[r][j] = unpk(acc[r][j]);
        float row[4][4];
        #pragma unroll
        for (int j = 0; j < 4; j++) {
            float bj = (&bb.x)[j];
            row[0][j] = fmaxf(v[0][j].x + bj, 0.f);
            row[1][j] = fmaxf(v[0][j].y + bj, 0.f);
            row[2][j] = fmaxf(v[1][j].x + bj, 0.f);
            row[3][j] = fmaxf(v[1][j].y + bj, 0.f);
        }
        const int m0 = 4 * ty;
        if (want_h) {
            #pragma unroll
            for (int r = 0; r < 4; r++)
                *(float4*)&h[(size_t)(m0 + r) * O + c] =
                    make_float4(row[r][0], row[r][1], row[r][2], row[r][3]);
        }
        if (want_hT) {
            #pragma unroll
            for (int j = 0; j < 4; j++)
                *(float4*)&hT[(size_t)(c + j) * NNODES + m0] =
                    make_float4(row[0][j], row[1][j], row[2][j], row[3][j]);
        }
    }
}

// ================= fused FCN head =================
__global__ __launch_bounds__(256) void head_fused(
    const float* __restrict__ h3, const int* __restrict__ batch,
    const float* __restrict__ W1, const float* __restrict__ c1,
    const float* __restrict__ W2, const float* __restrict__ c2,
    const float* __restrict__ W3, const float* __restrict__ c3,
    const float* __restrict__ W4, const float* __restrict__ c4,
    float* __restrict__ out)
{
    __shared__ float gS[100];
    __shared__ float s1[1000];
    __shared__ float part[200];
    __shared__ float s2[100];
    __shared__ float s3[50];
    __shared__ int   sb[NNODES];

    gdc_wait();

    const int g = blockIdx.x;
    const int t = threadIdx.x;

    if (t < NNODES) sb[t] = batch[t];
    __syncthreads();

    if (t < 100) {
        float a = 0.f;
        for (int n = 0; n < NNODES; n++)
            if (sb[n] == g) a += h3[n * 100 + t];
        gS[t] = a;
    }
    __syncthreads();

    for (int f = t; f < 1000; f += 256) {
        float a = c1[f];
        for (int k = 0; k < 100; k++) a += gS[k] * W1[k * 1000 + f];
        s1[f] = fmaxf(a, 0.f);
    }
    __syncthreads();

    if (t < 200) {
        int f = t % 100, hh = t / 100;
        float a = 0.f;
        int k0 = hh * 500;
        for (int k = k0; k < k0 + 500; k++) a += s1[k] * W2[k * 100 + f];
        part[t] = a;
    }
    __syncthreads();
    if (t < 100) s2[t] = fmaxf(part[t] + part[100 + t] + c2[t], 0.f);
    __syncthreads();

    if (t < 50) {
        float a = c3[t];
        for (int k = 0; k < 100; k++) a += s2[k] * W3[k * 50 + t];
        s3[t] = fmaxf(a, 0.f);
    }
    __syncthreads();

    if (t < 32) {
        float a = (t < 50) ? s3[t] * W4[t] : 0.f;
        if (t + 32 < 50) a += s3[t + 32] * W4[t + 32];
        #pragma unroll
        for (int o = 16; o > 0; o >>= 1)
            a += __shfl_xor_sync(0xffffffffu, a, o);
        if (t == 0) out[g] = a + c4[0];
    }
}

// ---------------- launch (7 PDL-chained kernels) ----------------
extern "C" void kernel_launch(void* const* d_in, const int* in_sizes, int n_in,
                              void* d_out, int out_size)
{
    const float* x     = (const float*)d_in[0];
    const int*   eidx  = (const int*)  d_in[1];
    const float* eattr = (const float*)d_in[2];
    const int*   batch = (const int*)  d_in[3];
    const float *We1 = (const float*)d_in[4],  *be1 = (const float*)d_in[5];
    const float *ro1 = (const float*)d_in[6],  *b1  = (const float*)d_in[7];
    const float *We2 = (const float*)d_in[8],  *be2 = (const float*)d_in[9];
    const float *ro2 = (const float*)d_in[10], *b2  = (const float*)d_in[11];
    const float *We3 = (const float*)d_in[12], *be3 = (const float*)d_in[13];
    const float *ro3 = (const float*)d_in[14], *b3  = (const float*)d_in[15];
    const float *W1  = (const float*)d_in[16], *c1  = (const float*)d_in[17];
    const float *W2  = (const float*)d_in[18], *c2  = (const float*)d_in[19];
    const float *W3  = (const float*)d_in[20], *c3  = (const float*)d_in[21];
    const float *W4  = (const float*)d_in[22], *c4  = (const float*)d_in[23];

    float *Y, *Yacc, *h1T, *h2T, *h3;
    cudaGetSymbolAddress((void**)&Y,    g_Y);
    cudaGetSymbolAddress((void**)&Yacc, g_Yacc);
    cudaGetSymbolAddress((void**)&h1T,  g_h1T);
    cudaGetSymbolAddress((void**)&h2T,  g_h2T);
    cudaGetSymbolAddress((void**)&h3,   g_h3);
    float* Y2 = Yacc;
    float* Y3 = Yacc + NNODES * NC2;

    cudaLaunchAttribute attr;
    attr.id = cudaLaunchAttributeProgrammaticStreamSerialization;
    attr.val.programmaticStreamSerializationAllowed = 1;

    auto mkcfg = [&](int gx, int gy, int nt) {
        cudaLaunchConfig_t cf{};
        cf.gridDim  = dim3((unsigned)gx, (unsigned)gy, 1);
        cf.blockDim = dim3((unsigned)nt, 1, 1);
        cf.dynamicSmemBytes = 0;
        cf.stream = 0;
        cf.attrs = &attr;
        cf.numAttrs = 1;
        return cf;
    };

    cudaLaunchConfig_t cf;

    // 1) layer-1 GEMM + prep + accumulator zeroing
    cf = mkcfg(96, 1, 128);
    cudaLaunchKernelEx(&cf, gemm1, x, eidx, eattr, We1, be1, ro1, Y);

    // 2) combine layer 1 -> h1T
    cf = mkcfg(CB1, 1, 128);
    cudaLaunchKernelEx(&cf, combine_gemm, (const float*)Y, O1, b1,
                       (float*)nullptr, h1T, 0, 1);

    // 3) layer-2 GEMM, split-K atomic -> Y2
    cf = mkcfg(TILES2, S2, 128);
    cudaLaunchKernelEx(&cf, gemm_atomic, (const float*)h1T, 2000, O2,
                       We2, be2, ro2, Y2, KC2);

    // 4) combine layer 2 -> h2T
    cf = mkcfg(CB2, 1, 128);
    cudaLaunchKernelEx(&cf, combine_gemm, (const float*)Y2, O2, b2,
                       (float*)nullptr, h2T, 0, 1);

    // 5) layer-3 GEMM, split-K atomic -> Y3
    cf = mkcfg(TILES3, S3, 128);
    cudaLaunchKernelEx(&cf, gemm_atomic, (const float*)h2T, 500, O3,
                       We3, be3, ro3, Y3, KC3);

    // 6) combine layer 3 -> h3
    cf = mkcfg(CB3, 1, 128);
    cudaLaunchKernelEx(&cf, combine_gemm, (const float*)Y3, O3, b3,
                       h3, (float*)nullptr, 1, 0);

    // 7) head
    cf = mkcfg(NGRAPH, 1, 256);
    cudaLaunchKernelEx(&cf, head_fused, (const float*)h3, batch, W1, c1,
                       W2, c2, W3, c3, W4, c4, (float*)d_out);
}

// round 10
// speedup vs baseline: 1.3722x; 1.0223x over previous
#include <cuda_runtime.h>
#include <cstdint>

#define NNODES 64
#define NEDGES 128
#define NGRAPH 4

typedef unsigned long long ull;

#define O1 2000
#define O2 500
#define O3 100
#define NC1 12000
#define NC2 3000
#define NC3 600
#define S2 24
#define KC2 84
#define S3 32
#define KC3 16
#define TILES2 24
#define TILES3 5
#define CB1 63
#define CB2 16
#define CB3 4

// ---------------- scratch ----------------
__device__ float g_Y   [NNODES * NC1];
__device__ float g_Yacc[NNODES * NC2 + NNODES * NC3];
__device__ float g_Pt  [384 * NNODES];
__device__ float g_h1T [O1 * NNODES];
__device__ float g_h2T [O2 * NNODES];
__device__ float g_h3  [NNODES * O3];

// ---------------- helpers ----------------
__device__ __forceinline__ void gdc_wait() {
    asm volatile("griddepcontrol.wait;" ::: "memory");
}
__device__ __forceinline__ void gdc_launch() {
    asm volatile("griddepcontrol.launch_dependents;" ::: "memory");
}
__device__ __forceinline__ ull dup2(float x) {
    ull r; asm("mov.b64 %0, {%1, %1};" : "=l"(r) : "f"(x)); return r;
}
__device__ __forceinline__ void fma2(ull &d, ull a, ull b) {
    asm("fma.rn.f32x2 %0, %1, %2, %3;" : "=l"(d) : "l"(a), "l"(b), "l"(d));
}
__device__ __forceinline__ float2 unpk(ull v) {
    float2 r; asm("mov.b64 {%0, %1}, %2;" : "=f"(r.x), "=f"(r.y) : "l"(v)); return r;
}
__device__ __forceinline__ void cpa16(void* dst, const void* src) {
    uint32_t d = (uint32_t)__cvta_generic_to_shared(dst);
    asm volatile("cp.async.cg.shared.global [%0], [%1], 16;\n" :: "r"(d), "l"(src));
}
__device__ __forceinline__ void cpa_commit() {
    asm volatile("cp.async.commit_group;\n" ::: "memory");
}
template<int N> __device__ __forceinline__ void cpa_wait() {
    asm volatile("cp.async.wait_group %0;\n" :: "n"(N) : "memory");
}

// ================= gemm1: K=9 special; fuses prep (Pt build, Yacc zero) =================
__global__ __launch_bounds__(128) void gemm1(
    const float* __restrict__ x, const int* __restrict__ eidx,
    const float* __restrict__ eattr,
    const float* __restrict__ We, const float* __restrict__ be,
    const float* __restrict__ root, float* __restrict__ Y)
{
    __shared__ float As[16][68];
    __shared__ float Bs[16][128];

    gdc_wait();
    gdc_launch();

    const int t = threadIdx.x;

    {
        float4* Z4 = (float4*)g_Yacc;
        const int tot4 = (NNODES * NC2 + NNODES * NC3) / 4;
        for (int i = blockIdx.x * 128 + t; i < tot4; i += 96 * 128)
            Z4[i] = make_float4(0.f, 0.f, 0.f, 0.f);
    }

    if (blockIdx.x == 94) {
        for (int i = t; i < 384 * NNODES; i += 128) {
            int r = i >> 6, n = i & 63;
            g_Pt[i] = (r >= 320 && (r - 320) == n) ? 1.f : 0.f;
        }
        __syncthreads();
        if (t < NEDGES) {
            int s = eidx[t], d = eidx[NEDGES + t];
            #pragma unroll
            for (int j = 0; j < 4; j++)
                atomicAdd(&g_Pt[(s * 5 + j) * NNODES + d], eattr[t * 4 + j]);
            atomicAdd(&g_Pt[(s * 5 + 4) * NNODES + d], 1.f);
        }
        return;
    }
    if (blockIdx.x >= 94) return;

    const int c0 = blockIdx.x * 128;

    {
        const int kkB   = t >> 3;
        const int cbase = (t & 7) * 16;
        const float4 z4 = make_float4(0.f, 0.f, 0.f, 0.f);
        #pragma unroll
        for (int i = 0; i < 4; i++) {
            int cl = cbase + 4 * i;
            int c  = c0 + cl;
            float4* bd = (float4*)&Bs[kkB][cl];
            if (kkB < 9 && c < NC1) {
                int blk = c / O1;
                int o   = c - blk * O1;
                const float* P = (blk < 4) ? (We + (size_t)blk * 9 * O1)
                                           : ((blk == 4) ? be : root);
                cpa16(bd, P + (size_t)kkB * O1 + o);
            } else *bd = z4;
        }
        cpa_commit();
    }
    if (t < NNODES) {
        #pragma unroll
        for (int a = 0; a < 9; a++) As[a][t] = x[t * 9 + a];
    }
    cpa_wait<0>();
    __syncthreads();

    const int tx = t & 15;
    const int ty = t >> 4;
    ull acc[4][8];
    #pragma unroll
    for (int r = 0; r < 4; r++)
        #pragma unroll
        for (int j = 0; j < 8; j++) acc[r][j] = 0ull;

    #pragma unroll
    for (int kk = 0; kk < 9; kk++) {
        const float* as = &As[kk][8 * ty];
        ull a0 = *(const ull*)(as);
        ull a1 = *(const ull*)(as + 2);
        ull a2 = *(const ull*)(as + 4);
        ull a3 = *(const ull*)(as + 6);
        float4 bL = *(const float4*)&Bs[kk][4 * tx];
        float4 bH = *(const float4*)&Bs[kk][64 + 4 * tx];
        ull b0 = dup2(bL.x), b1 = dup2(bL.y), b2 = dup2(bL.z), b3 = dup2(bL.w);
        ull b4 = dup2(bH.x), b5 = dup2(bH.y), b6 = dup2(bH.z), b7 = dup2(bH.w);
        fma2(acc[0][0], a0, b0); fma2(acc[0][1], a0, b1); fma2(acc[0][2], a0, b2); fma2(acc[0][3], a0, b3);
        fma2(acc[0][4], a0, b4); fma2(acc[0][5], a0, b5); fma2(acc[0][6], a0, b6); fma2(acc[0][7], a0, b7);
        fma2(acc[1][0], a1, b0); fma2(acc[1][1], a1, b1); fma2(acc[1][2], a1, b2); fma2(acc[1][3], a1, b3);
        fma2(acc[1][4], a1, b4); fma2(acc[1][5], a1, b5); fma2(acc[1][6], a1, b6); fma2(acc[1][7], a1, b7);
        fma2(acc[2][0], a2, b0); fma2(acc[2][1], a2, b1); fma2(acc[2][2], a2, b2); fma2(acc[2][3], a2, b3);
        fma2(acc[2][4], a2, b4); fma2(acc[2][5], a2, b5); fma2(acc[2][6], a2, b6); fma2(acc[2][7], a2, b7);
        fma2(acc[3][0], a3, b0); fma2(acc[3][1], a3, b1); fma2(acc[3][2], a3, b2); fma2(acc[3][3], a3, b3);
        fma2(acc[3][4], a3, b4); fma2(acc[3][5], a3, b5); fma2(acc[3][6], a3, b6); fma2(acc[3][7], a3, b7);
    }

    const int cL = c0 + 4 * tx;
    const int cH = c0 + 64 + 4 * tx;
    #pragma unroll
    for (int rp = 0; rp < 4; rp++) {
        int m = 8 * ty + 2 * rp;
        float2 vL0 = unpk(acc[rp][0]), vL1 = unpk(acc[rp][1]);
        float2 vL2 = unpk(acc[rp][2]), vL3 = unpk(acc[rp][3]);
        float2 vH0 = unpk(acc[rp][4]), vH1 = unpk(acc[rp][5]);
        float2 vH2 = unpk(acc[rp][6]), vH3 = unpk(acc[rp][7]);
        if (cL < NC1) {
            *(float4*)&Y[(size_t)m       * NC1 + cL] = make_float4(vL0.x, vL1.x, vL2.x, vL3.x);
            *(float4*)&Y[(size_t)(m + 1) * NC1 + cL] = make_float4(vL0.y, vL1.y, vL2.y, vL3.y);
        }
        if (cH < NC1) {
            *(float4*)&Y[(size_t)m       * NC1 + cH] = make_float4(vH0.x, vH1.x, vH2.x, vH3.x);
            *(float4*)&Y[(size_t)(m + 1) * NC1 + cH] = make_float4(vH0.y, vH1.y, vH2.y, vH3.y);
        }
    }
}

// ================= gemm_atomic: split-K GEMM, atomicAdd epilogue =================
__global__ __launch_bounds__(128) void gemm_atomic(
    const float* __restrict__ AT, int K, int O,
    const float* __restrict__ We, const float* __restrict__ be,
    const float* __restrict__ root, float* __restrict__ Yacc, int kChunk)
{
    __shared__ float As[3][16][68];
    __shared__ float Bs[3][16][128];

    gdc_wait();
    gdc_launch();

    const int t    = threadIdx.x;
    const int NC   = 6 * O;
    const int c0   = blockIdx.x * 128;
    const int k0   = blockIdx.y * kChunk;
    const int kend = min(k0 + kChunk, K);
    const int nsteps = (kend - k0 + 15) >> 4;

    const int kkB   = t >> 3;
    const int cbase = (t & 7) * 16;
    const float4 z4 = make_float4(0.f, 0.f, 0.f, 0.f);

    auto stage = [&](int s, int buf) {
        const int kt = k0 + s * 16;
        const int kb = kend - kt;
        #pragma unroll
        for (int i = 0; i < 4; i++) {
            int cl = cbase + 4 * i;
            int c  = c0 + cl;
            float4* bd = (float4*)&Bs[buf][kkB][cl];
            if (kkB < kb && c < NC) {
                int blk = c / O;
                int o   = c - blk * O;
                const float* P = (blk < 4) ? (We + (size_t)blk * K * O)
                                           : ((blk == 4) ? be : root);
                cpa16(bd, P + (size_t)(kt + kkB) * O + o);
            } else *bd = z4;
        }
        #pragma unroll
        for (int i = 0; i < 2; i++) {
            int q  = t + 128 * i;
            int kk = q >> 4, m4 = (q & 15) * 4;
            float4* ad = (float4*)&As[buf][kk][m4];
            if (kk < kb) cpa16(ad, AT + (size_t)(kt + kk) * NNODES + m4);
            else         *ad = z4;
        }
        cpa_commit();
    };

    stage(0, 0);
    if (nsteps > 1) stage(1, 1);

    const int tx = t & 15;
    const int ty = t >> 4;
    ull acc[4][8];
    #pragma unroll
    for (int r = 0; r < 4; r++)
        #pragma unroll
        for (int j = 0; j < 8; j++) acc[r][j] = 0ull;

    for (int s = 0; s < nsteps; s++) {
        const int buf = s % 3;
        if (s + 2 < nsteps)      { stage(s + 2, (s + 2) % 3); cpa_wait<2>(); }
        else if (s + 1 < nsteps) { cpa_wait<1>(); }
        else                     { cpa_wait<0>(); }
        __syncthreads();

        #pragma unroll
        for (int kk = 0; kk < 16; kk++) {
            const float* as = &As[buf][kk][8 * ty];
            ull a0 = *(const ull*)(as);
            ull a1 = *(const ull*)(as + 2);
            ull a2 = *(const ull*)(as + 4);
            ull a3 = *(const ull*)(as + 6);
            float4 bL = *(const float4*)&Bs[buf][kk][4 * tx];
            float4 bH = *(const float4*)&Bs[buf][kk][64 + 4 * tx];
            ull b0 = dup2(bL.x), b1 = dup2(bL.y), b2 = dup2(bL.z), b3 = dup2(bL.w);
            ull b4 = dup2(bH.x), b5 = dup2(bH.y), b6 = dup2(bH.z), b7 = dup2(bH.w);
            fma2(acc[0][0], a0, b0); fma2(acc[0][1], a0, b1); fma2(acc[0][2], a0, b2); fma2(acc[0][3], a0, b3);
            fma2(acc[0][4], a0, b4); fma2(acc[0][5], a0, b5); fma2(acc[0][6], a0, b6); fma2(acc[0][7], a0, b7);
            fma2(acc[1][0], a1, b0); fma2(acc[1][1], a1, b1); fma2(acc[1][2], a1, b2); fma2(acc[1][3], a1, b3);
            fma2(acc[1][4], a1, b4); fma2(acc[1][5], a1, b5); fma2(acc[1][6], a1, b6); fma2(acc[1][7], a1, b7);
            fma2(acc[2][0], a2, b0); fma2(acc[2][1], a2, b1); fma2(acc[2][2], a2, b2); fma2(acc[2][3], a2, b3);
            fma2(acc[2][4], a2, b4); fma2(acc[2][5], a2, b5); fma2(acc[2][6], a2, b6); fma2(acc[2][7], a2, b7);
            fma2(acc[3][0], a3, b0); fma2(acc[3][1], a3, b1); fma2(acc[3][2], a3, b2); fma2(acc[3][3], a3, b3);
            fma2(acc[3][4], a3, b4); fma2(acc[3][5], a3, b5); fma2(acc[3][6], a3, b6); fma2(acc[3][7], a3, b7);
        }
        __syncthreads();
    }

    const int cL = c0 + 4 * tx;
    const int cH = c0 + 64 + 4 * tx;
    #pragma unroll
    for (int rp = 0; rp < 4; rp++) {
        int m = 8 * ty + 2 * rp;
        float2 v[8];
        #pragma unroll
        for (int j = 0; j < 8; j++) v[j] = unpk(acc[rp][j]);
        if (cL < NC) {
            #pragma unroll
            for (int j = 0; j < 4; j++) {
                atomicAdd(&Yacc[(size_t)m       * NC + cL + j], v[j].x);
                atomicAdd(&Yacc[(size_t)(m + 1) * NC + cL + j], v[j].y);
            }
        }
        if (cH < NC) {
            #pragma unroll
            for (int j = 0; j < 4; j++) {
                atomicAdd(&Yacc[(size_t)m       * NC + cH + j], v[4 + j].x);
                atomicAdd(&Yacc[(size_t)(m + 1) * NC + cH + j], v[4 + j].y);
            }
        }
    }
}

// ================= combine: h = relu(P^T @ Yg + b), BN=32, K=384, 6-deep pipeline =================
__global__ __launch_bounds__(128) void combine_gemm(
    const float* __restrict__ Y, int O, const float* __restrict__ bias,
    float* __restrict__ h, float* __restrict__ hT, int want_h, int want_hT)
{
    __shared__ float As[6][16][68];
    __shared__ float Bs[6][16][32];

    gdc_wait();
    gdc_launch();

    const int t  = threadIdx.x;
    const int NC = 6 * O;
    const int c0 = blockIdx.x * 32;

    const int kkB = t >> 3;
    const int clB = (t & 7) * 4;
    const bool bvalid = (c0 + clB < O);
    const float4 z4 = make_float4(0.f, 0.f, 0.f, 0.f);

    auto stage = [&](int s, int buf) {
        int r = s * 16 + kkB;
        int sN, jb;
        if (r < 320) { sN = r / 5; jb = r - 5 * sN; }
        else         { sN = r - 320; jb = 5; }
        float4* bd = (float4*)&Bs[buf][kkB][clB];
        if (bvalid) cpa16(bd, Y + (size_t)sN * NC + (size_t)jb * O + c0 + clB);
        else        *bd = z4;
        #pragma unroll
        for (int i = 0; i < 2; i++) {
            int q  = t + 128 * i;
            int kk = q >> 4, m4 = (q & 15) * 4;
            cpa16(&As[buf][kk][m4], g_Pt + (size_t)(s * 16 + kk) * NNODES + m4);
        }
        cpa_commit();
    };

    // prologue: 5 stages ahead
    stage(0, 0); stage(1, 1); stage(2, 2); stage(3, 3); stage(4, 4);

    const int tx = t & 7;
    const int ty = t >> 3;
    ull acc[2][4];
    #pragma unroll
    for (int r = 0; r < 2; r++)
        #pragma unroll
        for (int j = 0; j < 4; j++) acc[r][j] = 0ull;

    for (int s = 0; s < 24; s++) {
        const int buf = s % 6;
        if (s + 5 < 24) { stage(s + 5, (s + 5) % 6); cpa_wait<5>(); }
        else {
            const int rem = 23 - s;   // stages still in flight beyond current
            if      (rem == 4) cpa_wait<4>();
            else if (rem == 3) cpa_wait<3>();
            else if (rem == 2) cpa_wait<2>();
            else if (rem == 1) cpa_wait<1>();
            else               cpa_wait<0>();
        }
        __syncthreads();

        #pragma unroll
        for (int kk = 0; kk < 16; kk++) {
            const float* as = &As[buf][kk][0];
            ull a0 = *(const ull*)(as + 4 * ty);
            ull a1 = *(const ull*)(as + 4 * ty + 2);
            float4 b = *(const float4*)&Bs[buf][kk][4 * tx];
            ull b0 = dup2(b.x), b1 = dup2(b.y), b2 = dup2(b.z), b3 = dup2(b.w);
            fma2(acc[0][0], a0, b0); fma2(acc[0][1], a0, b1);
            fma2(acc[0][2], a0, b2); fma2(acc[0][3], a0, b3);
            fma2(acc[1][0], a1, b0); fma2(acc[1][1], a1, b1);
            fma2(acc[1][2], a1, b2); fma2(acc[1][3], a1, b3);
        }
        __syncthreads();
    }

    const int c = c0 + 4 * tx;
    if (c < O) {
        float4 bb = *(const float4*)&bias[c];
        float2 v[2][4];
        #pragma unroll
        for (int r = 0; r < 2; r++)
            #pragma unroll
            for (int j = 0; j < 4; j++) v[r][j] = unpk(acc[r][j]);
        float row[4][4];
        #pragma unroll
        for (int j = 0; j < 4; j++) {
            float bj = (&bb.x)[j];
            row[0][j] = fmaxf(v[0][j].x + bj, 0.f);
            row[1][j] = fmaxf(v[0][j].y + bj, 0.f);
            row[2][j] = fmaxf(v[1][j].x + bj, 0.f);
            row[3][j] = fmaxf(v[1][j].y + bj, 0.f);
        }
        const int m0 = 4 * ty;
        if (want_h) {
            #pragma unroll
            for (int r = 0; r < 4; r++)
                *(float4*)&h[(size_t)(m0 + r) * O + c] =
                    make_float4(row[r][0], row[r][1], row[r][2], row[r][3]);
        }
        if (want_hT) {
            #pragma unroll
            for (int j = 0; j < 4; j++)
                *(float4*)&hT[(size_t)(c + j) * NNODES + m0] =
                    make_float4(row[0][j], row[1][j], row[2][j], row[3][j]);
        }
    }
}

// ================= fused FCN head =================
__global__ __launch_bounds__(256) void head_fused(
    const float* __restrict__ h3, const int* __restrict__ batch,
    const float* __restrict__ W1, const float* __restrict__ c1,
    const float* __restrict__ W2, const float* __restrict__ c2,
    const float* __restrict__ W3, const float* __restrict__ c3,
    const float* __restrict__ W4, const float* __restrict__ c4,
    float* __restrict__ out)
{
    __shared__ float gS[100];
    __shared__ float s1[1000];
    __shared__ float part[200];
    __shared__ float s2[100];
    __shared__ float s3[50];
    __shared__ int   sb[NNODES];

    gdc_wait();

    const int g = blockIdx.x;
    const int t = threadIdx.x;

    if (t < NNODES) sb[t] = batch[t];
    __syncthreads();

    if (t < 100) {
        float a = 0.f;
        for (int n = 0; n < NNODES; n++)
            if (sb[n] == g) a += h3[n * 100 + t];
        gS[t] = a;
    }
    __syncthreads();

    for (int f = t; f < 1000; f += 256) {
        float a = c1[f];
        for (int k = 0; k < 100; k++) a += gS[k] * W1[k * 1000 + f];
        s1[f] = fmaxf(a, 0.f);
    }
    __syncthreads();

    if (t < 200) {
        int f = t % 100, hh = t / 100;
        float a = 0.f;
        int k0 = hh * 500;
        for (int k = k0; k < k0 + 500; k++) a += s1[k] * W2[k * 100 + f];
        part[t] = a;
    }
    __syncthreads();
    if (t < 100) s2[t] = fmaxf(part[t] + part[100 + t] + c2[t], 0.f);
    __syncthreads();

    if (t < 50) {
        float a = c3[t];
        for (int k = 0; k < 100; k++) a += s2[k] * W3[k * 50 + t];
        s3[t] = fmaxf(a, 0.f);
    }
    __syncthreads();

    if (t < 32) {
        float a = (t < 50) ? s3[t] * W4[t] : 0.f;
        if (t + 32 < 50) a += s3[t + 32] * W4[t + 32];
        #pragma unroll
        for (int o = 16; o > 0; o >>= 1)
            a += __shfl_xor_sync(0xffffffffu, a, o);
        if (t == 0) out[g] = a + c4[0];
    }
}

// ---------------- launch (7 PDL-chained kernels) ----------------
extern "C" void kernel_launch(void* const* d_in, const int* in_sizes, int n_in,
                              void* d_out, int out_size)
{
    const float* x     = (const float*)d_in[0];
    const int*   eidx  = (const int*)  d_in[1];
    const float* eattr = (const float*)d_in[2];
    const int*   batch = (const int*)  d_in[3];
    const float *We1 = (const float*)d_in[4],  *be1 = (const float*)d_in[5];
    const float *ro1 = (const float*)d_in[6],  *b1  = (const float*)d_in[7];
    const float *We2 = (const float*)d_in[8],  *be2 = (const float*)d_in[9];
    const float *ro2 = (const float*)d_in[10], *b2  = (const float*)d_in[11];
    const float *We3 = (const float*)d_in[12], *be3 = (const float*)d_in[13];
    const float *ro3 = (const float*)d_in[14], *b3  = (const float*)d_in[15];
    const float *W1  = (const float*)d_in[16], *c1  = (const float*)d_in[17];
    const float *W2  = (const float*)d_in[18], *c2  = (const float*)d_in[19];
    const float *W3  = (const float*)d_in[20], *c3  = (const float*)d_in[21];
    const float *W4  = (const float*)d_in[22], *c4  = (const float*)d_in[23];

    float *Y, *Yacc, *h1T, *h2T, *h3;
    cudaGetSymbolAddress((void**)&Y,    g_Y);
    cudaGetSymbolAddress((void**)&Yacc, g_Yacc);
    cudaGetSymbolAddress((void**)&h1T,  g_h1T);
    cudaGetSymbolAddress((void**)&h2T,  g_h2T);
    cudaGetSymbolAddress((void**)&h3,   g_h3);
    float* Y2 = Yacc;
    float* Y3 = Yacc + NNODES * NC2;

    cudaLaunchAttribute attr;
    attr.id = cudaLaunchAttributeProgrammaticStreamSerialization;
    attr.val.programmaticStreamSerializationAllowed = 1;

    auto mkcfg = [&](int gx, int gy, int nt) {
        cudaLaunchConfig_t cf{};
        cf.gridDim  = dim3((unsigned)gx, (unsigned)gy, 1);
        cf.blockDim = dim3((unsigned)nt, 1, 1);
        cf.dynamicSmemBytes = 0;
        cf.stream = 0;
        cf.attrs = &attr;
        cf.numAttrs = 1;
        return cf;
    };

    cudaLaunchConfig_t cf;

    cf = mkcfg(96, 1, 128);
    cudaLaunchKernelEx(&cf, gemm1, x, eidx, eattr, We1, be1, ro1, Y);

    cf = mkcfg(CB1, 1, 128);
    cudaLaunchKernelEx(&cf, combine_gemm, (const float*)Y, O1, b1,
                       (float*)nullptr, h1T, 0, 1);

    cf = mkcfg(TILES2, S2, 128);
    cudaLaunchKernelEx(&cf, gemm_atomic, (const float*)h1T, 2000, O2,
                       We2, be2, ro2, Y2, KC2);

    cf = mkcfg(CB2, 1, 128);
    cudaLaunchKernelEx(&cf, combine_gemm, (const float*)Y2, O2, b2,
                       (float*)nullptr, h2T, 0, 1);

    cf = mkcfg(TILES3, S3, 128);
    cudaLaunchKernelEx(&cf, gemm_atomic, (const float*)h2T, 500, O3,
                       We3, be3, ro3, Y3, KC3);

    cf = mkcfg(CB3, 1, 128);
    cudaLaunchKernelEx(&cf, combine_gemm, (const float*)Y3, O3, b3,
                       h3, (float*)nullptr, 1, 0);

    cf = mkcfg(NGRAPH, 1, 256);
    cudaLaunchKernelEx(&cf, head_fused, (const float*)h3, batch, W1, c1,
                       W2, c2, W3, c3, W4, c4, (float*)d_out);
}